// round 1
// baseline (speedup 1.0000x reference)
#include <cuda_runtime.h>
#include <math.h>

#define NB 4
#define NC 512
#define NL 2048
#define NCI 512
#define NH 8
#define ND 64

// Scratch (device globals; no allocations allowed)
__device__ float d_proj[3 * NB * NCI * NL];   // [which][b][ci][l]; which: 0=g, 1=theta, 2=phi
__device__ float d_y[NB * NCI * NL];          // attention output [b][ci][l]
__device__ float d_wy[NB * NC * NL];          // final conv output (pre-BN)
__device__ float d_bnmean[NC];
__device__ float d_bnrstd[NC];

// ---------------------------------------------------------------------------
// Shared 128x64 fp32 GEMM body: out[m,n] = sum_k A[m,k] * X[k,n] + bias[m]
// A: [512,512] row-major, X: [512,NL], out: [512,NL]. BK=16, 256 threads,
// 8m x 4n per thread.
// ---------------------------------------------------------------------------
__device__ __forceinline__ void gemm_body(
    const float* __restrict__ A,
    const float* __restrict__ X,
    const float* __restrict__ bias,
    float* __restrict__ out)
{
    __shared__ float As[16 * 128];
    __shared__ float Bs[16 * 64];
    const int tid = threadIdx.x;
    const int tx = tid & 15;
    const int ty = tid >> 4;
    const int m0 = blockIdx.y * 128;
    const int n0 = blockIdx.x * 64;

    float acc[8][4];
#pragma unroll
    for (int i = 0; i < 8; i++)
#pragma unroll
        for (int j = 0; j < 4; j++) acc[i][j] = 0.f;

    const int ag = tid & 3;    // A k-group (float4)
    const int am = tid >> 2;   // 0..63
    const int bn_ = tid & 63;
    const int bk = tid >> 6;   // 0..3

    for (int k0 = 0; k0 < 512; k0 += 16) {
#pragma unroll
        for (int r = 0; r < 2; r++) {
            int mm = am + r * 64;
            float4 a = *reinterpret_cast<const float4*>(&A[(m0 + mm) * 512 + k0 + ag * 4]);
            As[(ag * 4 + 0) * 128 + mm] = a.x;
            As[(ag * 4 + 1) * 128 + mm] = a.y;
            As[(ag * 4 + 2) * 128 + mm] = a.z;
            As[(ag * 4 + 3) * 128 + mm] = a.w;
        }
#pragma unroll
        for (int r = 0; r < 4; r++)
            Bs[(bk + r * 4) * 64 + bn_] = X[(k0 + bk + r * 4) * NL + n0 + bn_];
        __syncthreads();
#pragma unroll
        for (int kk = 0; kk < 16; kk++) {
            float4 a0 = *reinterpret_cast<const float4*>(&As[kk * 128 + ty * 8]);
            float4 a1 = *reinterpret_cast<const float4*>(&As[kk * 128 + ty * 8 + 4]);
            float4 bv = *reinterpret_cast<const float4*>(&Bs[kk * 64 + tx * 4]);
            float amr[8] = {a0.x, a0.y, a0.z, a0.w, a1.x, a1.y, a1.z, a1.w};
            float bnr[4] = {bv.x, bv.y, bv.z, bv.w};
#pragma unroll
            for (int i = 0; i < 8; i++)
#pragma unroll
                for (int j = 0; j < 4; j++) acc[i][j] = fmaf(amr[i], bnr[j], acc[i][j]);
        }
        __syncthreads();
    }
#pragma unroll
    for (int i = 0; i < 8; i++) {
        int m = m0 + ty * 8 + i;
        float bi = bias[m];
        float4 o = make_float4(acc[i][0] + bi, acc[i][1] + bi, acc[i][2] + bi, acc[i][3] + bi);
        *reinterpret_cast<float4*>(&out[m * NL + n0 + tx * 4]) = o;
    }
}

// grid: (NL/64=32, 512/128=4, 3*NB=12)
__global__ void __launch_bounds__(256) proj_kernel(
    const float* __restrict__ x,
    const float* __restrict__ gw, const float* __restrict__ gb,
    const float* __restrict__ tw, const float* __restrict__ tb,
    const float* __restrict__ pw, const float* __restrict__ pb)
{
    int z = blockIdx.z;
    int which = z >> 2;   // 0..2
    int b = z & 3;
    const float* A = (which == 0) ? gw : (which == 1) ? tw : pw;
    const float* bias = (which == 0) ? gb : (which == 1) ? tb : pb;
    gemm_body(A, x + (size_t)b * NC * NL, bias,
              d_proj + ((size_t)which * NB + b) * NCI * NL);
}

// grid: (32, 4, NB)
__global__ void __launch_bounds__(256) gemm2_kernel(
    const float* __restrict__ ww, const float* __restrict__ wb)
{
    int b = blockIdx.z;
    gemm_body(ww, d_y + (size_t)b * NCI * NL, wb, d_wy + (size_t)b * NC * NL);
}

// ---------------------------------------------------------------------------
// Flash attention: per (b,h), Q=theta^T [L,64], K=phi [64,L], V=g [64,L].
// q-tile=128, k-tile=64, 256 threads, thread tile 8q x 4{k|d}.
// grid: (NL/128=16, NB*NH=32). Dynamic smem ~99KB.
// ---------------------------------------------------------------------------
#define ATT_SMEM ((64 * 128 + 64 * 64 + 64 * 65 + 128 * 65) * 4)

__global__ void __launch_bounds__(256, 2) attn_kernel()
{
    extern __shared__ float sm[];
    float* Qs = sm;                  // [64 d][128 q], pitch 128
    float* Ks = Qs + 64 * 128;       // [64 d][64 k], pitch 64
    float* Vs = Ks + 64 * 64;        // [64 d][64 k], pitch 65
    float* Ps = Vs + 64 * 65;        // [128 q][64 k], pitch 65 (reused as [64 d][128 q] pitch 129)

    const int tid = threadIdx.x;
    const int tx = tid & 15;   // k/d dimension (4 each)
    const int ty = tid >> 4;   // q dimension (8 each)
    const int q0 = blockIdx.x * 128;
    const int bh = blockIdx.y;
    const int b = bh >> 3;
    const int h = bh & 7;

    const float* theta = d_proj + ((size_t)(1 * NB + b) * NCI + h * ND) * NL;
    const float* phi   = d_proj + ((size_t)(2 * NB + b) * NCI + h * ND) * NL;
    const float* gx    = d_proj + ((size_t)(0 * NB + b) * NCI + h * ND) * NL;

    // Load Q tile (scaled by 1/sqrt(D) here)
    for (int i = tid; i < 64 * 128; i += 256) {
        int d = i >> 7, q = i & 127;
        Qs[i] = theta[d * NL + q0 + q] * 0.125f;
    }

    float m[8], l[8], acc[8][4];
#pragma unroll
    for (int i = 0; i < 8; i++) {
        m[i] = -1e30f; l[i] = 0.f;
#pragma unroll
        for (int j = 0; j < 4; j++) acc[i][j] = 0.f;
    }

    for (int k0 = 0; k0 < NL; k0 += 64) {
        __syncthreads();  // prior-iter readers done (also orders Q load, iter 0)
        for (int i = tid; i < 64 * 64; i += 256) {
            int d = i >> 6, k = i & 63;
            float kv = phi[d * NL + k0 + k];
            float vv = gx[d * NL + k0 + k];
            Ks[d * 64 + k] = kv;
            Vs[d * 65 + k] = vv;
        }
        __syncthreads();

        // S = Q K : s[8q][4k]
        float s[8][4];
#pragma unroll
        for (int i = 0; i < 8; i++)
#pragma unroll
            for (int j = 0; j < 4; j++) s[i][j] = 0.f;

#pragma unroll 8
        for (int d = 0; d < 64; d++) {
            float4 qa = *reinterpret_cast<const float4*>(Qs + d * 128 + ty * 8);
            float4 qb = *reinterpret_cast<const float4*>(Qs + d * 128 + ty * 8 + 4);
            float4 kv = *reinterpret_cast<const float4*>(Ks + d * 64 + tx * 4);
            float qm[8] = {qa.x, qa.y, qa.z, qa.w, qb.x, qb.y, qb.z, qb.w};
            float kn[4] = {kv.x, kv.y, kv.z, kv.w};
#pragma unroll
            for (int i = 0; i < 8; i++)
#pragma unroll
                for (int j = 0; j < 4; j++) s[i][j] = fmaf(qm[i], kn[j], s[i][j]);
        }

        // Online softmax per q row (reduce across the 16 tx lanes)
#pragma unroll
        for (int qi = 0; qi < 8; qi++) {
            float tmax = fmaxf(fmaxf(s[qi][0], s[qi][1]), fmaxf(s[qi][2], s[qi][3]));
#pragma unroll
            for (int msk = 1; msk < 16; msk <<= 1)
                tmax = fmaxf(tmax, __shfl_xor_sync(0xffffffffu, tmax, msk));
            float mn = fmaxf(m[qi], tmax);
            float corr = __expf(m[qi] - mn);
            float psum = 0.f;
#pragma unroll
            for (int ki = 0; ki < 4; ki++) {
                float p = __expf(s[qi][ki] - mn);
                s[qi][ki] = p;
                psum += p;
            }
#pragma unroll
            for (int msk = 1; msk < 16; msk <<= 1)
                psum += __shfl_xor_sync(0xffffffffu, psum, msk);
            l[qi] = l[qi] * corr + psum;
            m[qi] = mn;
#pragma unroll
            for (int di = 0; di < 4; di++) acc[qi][di] *= corr;
            int row = ty * 8 + qi;
#pragma unroll
            for (int ki = 0; ki < 4; ki++) Ps[row * 65 + tx * 4 + ki] = s[qi][ki];
        }
        __syncthreads();

        // acc += P V^T : acc[8q][4d]
#pragma unroll 8
        for (int k = 0; k < 64; k++) {
            float vv[4];
#pragma unroll
            for (int di = 0; di < 4; di++) vv[di] = Vs[(tx * 4 + di) * 65 + k];
#pragma unroll
            for (int qi = 0; qi < 8; qi++) {
                float p = Ps[(ty * 8 + qi) * 65 + k];
#pragma unroll
                for (int di = 0; di < 4; di++) acc[qi][di] = fmaf(p, vv[di], acc[qi][di]);
            }
        }
    }
    __syncthreads();

    // Epilogue: normalize, transpose via smem (reuse Ps as [64 d][128 q] pitch 129)
#pragma unroll
    for (int qi = 0; qi < 8; qi++) {
        float inv = 1.0f / l[qi];
#pragma unroll
        for (int di = 0; di < 4; di++)
            Ps[(tx * 4 + di) * 129 + ty * 8 + qi] = acc[qi][di] * inv;
    }
    __syncthreads();

    float* yout = d_y + ((size_t)b * NCI + h * ND) * NL;
    for (int i = tid; i < 64 * 128; i += 256) {
        int d = i >> 7, q = i & 127;
        yout[d * NL + q0 + q] = Ps[d * 129 + q];
    }
}

// ---------------------------------------------------------------------------
// BatchNorm1d (training mode, biased stats) over (B, L) per channel.
// ---------------------------------------------------------------------------
__global__ void __launch_bounds__(256) bn_stats_kernel()
{
    const int c = blockIdx.x;
    const int tid = threadIdx.x;
    double s = 0.0, s2 = 0.0;
    for (int i = tid; i < NB * NL; i += 256) {
        int b = i >> 11, l = i & 2047;
        float v = d_wy[((size_t)b * NC + c) * NL + l];
        s += (double)v;
        s2 += (double)v * (double)v;
    }
    __shared__ double sh[256], sh2[256];
    sh[tid] = s; sh2[tid] = s2;
    __syncthreads();
    for (int off = 128; off > 0; off >>= 1) {
        if (tid < off) { sh[tid] += sh[tid + off]; sh2[tid] += sh2[tid + off]; }
        __syncthreads();
    }
    if (tid == 0) {
        double mean = sh[0] / (double)(NB * NL);
        double var = sh2[0] / (double)(NB * NL) - mean * mean;
        d_bnmean[c] = (float)mean;
        d_bnrstd[c] = (float)(1.0 / sqrt(var + 1e-5));
    }
}

__global__ void __launch_bounds__(256) bn_apply_kernel(
    const float* __restrict__ gamma, const float* __restrict__ beta,
    float* __restrict__ out)
{
    int idx = blockIdx.x * 256 + threadIdx.x;
    int c = (idx >> 11) & (NC - 1);
    out[idx] = (d_wy[idx] - d_bnmean[c]) * d_bnrstd[c] * gamma[c] + beta[c];
}

// ---------------------------------------------------------------------------
extern "C" void kernel_launch(void* const* d_in, const int* in_sizes, int n_in,
                              void* d_out, int out_size)
{
    const float* x     = (const float*)d_in[0];
    const float* gw    = (const float*)d_in[1];
    const float* gb    = (const float*)d_in[2];
    const float* tw    = (const float*)d_in[3];
    const float* tb    = (const float*)d_in[4];
    const float* pw    = (const float*)d_in[5];
    const float* pb    = (const float*)d_in[6];
    const float* ww    = (const float*)d_in[7];
    const float* wb    = (const float*)d_in[8];
    const float* gamma = (const float*)d_in[9];
    const float* beta  = (const float*)d_in[10];
    float* out = (float*)d_out;

    cudaFuncSetAttribute(attn_kernel, cudaFuncAttributeMaxDynamicSharedMemorySize, ATT_SMEM);

    proj_kernel<<<dim3(NL / 64, 4, 3 * NB), 256>>>(x, gw, gb, tw, tb, pw, pb);
    attn_kernel<<<dim3(NL / 128, NB * NH), 256, ATT_SMEM>>>();
    gemm2_kernel<<<dim3(NL / 64, 4, NB), 256>>>(ww, wb);
    bn_stats_kernel<<<NC, 256>>>();
    bn_apply_kernel<<<(NB * NC * NL) / 256, 256>>>(gamma, beta, out);
}